// round 10
// baseline (speedup 1.0000x reference)
#include <cuda_runtime.h>
#include <cstdint>

// Problem constants
#define Bsz 8
#define Tt  512
#define Dd  1024
#define Hh  16
#define DHh 64
#define Ll  4
#define Cc  10
#define Mrows (Bsz*Tt)   // 4096
#define BH   (Bsz*Hh)    // 128
#define INV_RD (1.0f/32.0f)

// ---------------- scratch (static device globals: allocation-free) ----------
__device__ float g_xa[Mrows*Dd];
__device__ float g_xb[Mrows*Dd];
__device__ float g_q [Mrows*Dd];
__device__ float g_k [Mrows*Dd];
__device__ float g_v [Mrows*Dd];
__device__ float g_s [(size_t)BH*Tt*Tt];   // 134 MB scores

// ---------------- tf32x3 helpers -------------------------------------------
__device__ __forceinline__ float2 f_hilo(float f) {
    uint32_t h;
    asm("cvt.rna.tf32.f32 %0, %1;" : "=r"(h) : "f"(f));
    float hf = __uint_as_float(h);
    float r  = f - hf;
    uint32_t l;
    asm("cvt.rna.tf32.f32 %0, %1;" : "=r"(l) : "f"(r));
    return make_float2(hf, __uint_as_float(l));
}

__device__ __forceinline__ void mma8(float c[4], const uint32_t a[4], const uint32_t b[2]) {
    asm volatile("mma.sync.aligned.m16n8k8.row.col.f32.tf32.tf32.f32 "
        "{%0,%1,%2,%3}, {%4,%5,%6,%7}, {%8,%9}, {%0,%1,%2,%3};"
        : "+f"(c[0]), "+f"(c[1]), "+f"(c[2]), "+f"(c[3])
        : "r"(a[0]), "r"(a[1]), "r"(a[2]), "r"(a[3]), "r"(b[0]), "r"(b[1]));
}

// ---------------- add positional encoding ----------------------------------
__global__ void add_pos_kernel(const float* __restrict__ x,
                               const float* __restrict__ pos,
                               float* __restrict__ out) {
    int i = blockIdx.x * blockDim.x + threadIdx.x;
    const int n4 = Mrows*Dd/4;
    if (i < n4) {
        float4 a = ((const float4*)x)[i];
        float4 p = ((const float4*)pos)[i % (Tt*Dd/4)];
        a.x += p.x; a.y += p.y; a.z += p.z; a.w += p.w;
        ((float4*)out)[i] = a;
    }
}

// ---------------- layernorm (in-place, one block per row) ------------------
__global__ void ln_kernel(float* __restrict__ x,
                          const float* __restrict__ g,
                          const float* __restrict__ b) {
    __shared__ float red[16];
    __shared__ float s_mv[2];
    int row = blockIdx.x;
    int tid = threadIdx.x;
    float4* xp = (float4*)(x + (size_t)row*Dd);
    float4 v = xp[tid];
    float s  = v.x+v.y+v.z+v.w;
    float sq = v.x*v.x+v.y*v.y+v.z*v.z+v.w*v.w;
    #pragma unroll
    for (int o=16;o;o>>=1){ s += __shfl_down_sync(0xffffffffu,s,o);
                            sq += __shfl_down_sync(0xffffffffu,sq,o); }
    int warp = tid>>5, lane = tid&31;
    if (!lane){ red[warp]=s; red[8+warp]=sq; }
    __syncthreads();
    if (tid < 32){
        float a = (lane<8)? red[lane]   : 0.f;
        float c = (lane<8)? red[8+lane] : 0.f;
        #pragma unroll
        for (int o=4;o;o>>=1){ a += __shfl_down_sync(0xffffffffu,a,o);
                               c += __shfl_down_sync(0xffffffffu,c,o); }
        if (!lane){
            float mean = a * (1.0f/Dd);
            float var  = c * (1.0f/Dd) - mean*mean;
            s_mv[0] = mean;
            s_mv[1] = rsqrtf(var + 1e-5f);
        }
    }
    __syncthreads();
    float mean = s_mv[0], rstd = s_mv[1];
    float4 gg = ((const float4*)g)[tid];
    float4 bb = ((const float4*)b)[tid];
    v.x = (v.x-mean)*rstd*gg.x + bb.x;
    v.y = (v.y-mean)*rstd*gg.y + bb.y;
    v.z = (v.z-mean)*rstd*gg.z + bb.z;
    v.w = (v.w-mean)*rstd*gg.w + bb.w;
    xp[tid] = v;
}

// ---------------- projection GEMM (tensor cores, tf32x3) -------------------
// C[4096,1024] = A[4096,1024] @ W[1024,1024]^T. 128x128 block, BK=32,
// 256 threads = 8 warps (2m x 4n), warp tile 64x32 (4 m-tiles x 4 n-tiles).
// smem holds (hi,lo) float2 per element; pitch 34 to dodge bank conflicts.
template<bool FCEPI>
__global__ void __launch_bounds__(256)
gemm_tc(const float* __restrict__ A, const float* __restrict__ W,
        const float* __restrict__ bias, float* __restrict__ C) {
    extern __shared__ float2 smraw[];
    float2* As = smraw;            // [128][34]
    float2* Bs = smraw + 128*34;   // [128][34]
    const int tid = threadIdx.x, lane = tid&31, warp = tid>>5;
    const int wm = (warp>>2)*64, wn = (warp&3)*32;
    const int gid = lane>>2, tig = lane&3;
    const int bm = blockIdx.y*128, bn = blockIdx.x*128;
    const int ldr = tid>>1, ldc = (tid&1)*16;
    const float* Ap = A + (size_t)(bm+ldr)*Dd + ldc;
    const float* Wp = W + (size_t)(bn+ldr)*Dd + ldc;
    float c[4][4][4] = {};
    float4 av[4], wv[4];
    #pragma unroll
    for (int i=0;i<4;i++){ av[i] = *(const float4*)(Ap + i*4);
                           wv[i] = *(const float4*)(Wp + i*4); }
    for (int k0=0;k0<Dd;k0+=32){
        __syncthreads();
        #pragma unroll
        for (int i=0;i<4;i++){
            const float* a4=(const float*)&av[i];
            const float* w4=(const float*)&wv[i];
            #pragma unroll
            for(int j=0;j<4;j++){
                As[ldr*34 + ldc + i*4 + j] = f_hilo(a4[j]);
                Bs[ldr*34 + ldc + i*4 + j] = f_hilo(w4[j]);
            }
        }
        __syncthreads();
        if (k0+32 < Dd){
            #pragma unroll
            for (int i=0;i<4;i++){ av[i] = *(const float4*)(Ap + k0+32 + i*4);
                                   wv[i] = *(const float4*)(Wp + k0+32 + i*4); }
        }
        #pragma unroll
        for (int k8=0;k8<4;k8++){
            const int kb = k8*8;
            uint32_t ahi[4][4], alo[4][4], bhi[4][2], blo[4][2];
            #pragma unroll
            for (int mt=0;mt<4;mt++){
                int mb = wm + mt*16 + gid;
                float2 f0 = As[mb*34 + kb+tig];
                float2 f1 = As[(mb+8)*34 + kb+tig];
                float2 f2 = As[mb*34 + kb+tig+4];
                float2 f3 = As[(mb+8)*34 + kb+tig+4];
                ahi[mt][0]=__float_as_uint(f0.x); alo[mt][0]=__float_as_uint(f0.y);
                ahi[mt][1]=__float_as_uint(f1.x); alo[mt][1]=__float_as_uint(f1.y);
                ahi[mt][2]=__float_as_uint(f2.x); alo[mt][2]=__float_as_uint(f2.y);
                ahi[mt][3]=__float_as_uint(f3.x); alo[mt][3]=__float_as_uint(f3.y);
            }
            #pragma unroll
            for (int nt=0;nt<4;nt++){
                int nb = wn + nt*8 + gid;
                float2 g0 = Bs[nb*34 + kb+tig];
                float2 g1 = Bs[nb*34 + kb+tig+4];
                bhi[nt][0]=__float_as_uint(g0.x); blo[nt][0]=__float_as_uint(g0.y);
                bhi[nt][1]=__float_as_uint(g1.x); blo[nt][1]=__float_as_uint(g1.y);
            }
            #pragma unroll
            for (int mt=0;mt<4;mt++)
                #pragma unroll
                for (int nt=0;nt<4;nt++){
                    mma8(c[mt][nt], ahi[mt], bhi[nt]);
                    mma8(c[mt][nt], alo[mt], bhi[nt]);
                    mma8(c[mt][nt], ahi[mt], blo[nt]);
                }
        }
    }
    #pragma unroll
    for (int mt=0;mt<4;mt++){
        #pragma unroll
        for (int nt=0;nt<4;nt++){
            int col = bn + wn + nt*8 + tig*2;
            #pragma unroll
            for (int half=0; half<2; half++){
                int row = bm + wm + mt*16 + gid + half*8;
                float2 val = make_float2(c[mt][nt][half*2], c[mt][nt][half*2+1]);
                if (FCEPI){
                    float2 bi = *(const float2*)(bias + col);
                    float2 r  = *(const float2*)(A + (size_t)row*Dd + col);
                    val.x = fmaxf(val.x+bi.x, 0.f) + r.x;
                    val.y = fmaxf(val.y+bi.y, 0.f) + r.y;
                }
                *(float2*)(C + (size_t)row*Dd + col) = val;
            }
        }
    }
}

// ---------------- attention scores (tensor cores, tf32x3) ------------------
// S[z,q,k] = (Q[q]·K[k])/32.  128x128 tile, K-dim=64 loaded in one shot.
// CSKIP: skip fully-masked causal tiles (bk tile strictly above bq tile).
template<bool SELF, bool CSKIP>
__global__ void __launch_bounds__(256)
scores_tc(const float* __restrict__ Q, const float* __restrict__ Kt,
          float* __restrict__ S) {
    if (CSKIP && blockIdx.x > blockIdx.y) return;
    extern __shared__ float2 smraw[];
    float2* Qs = smraw;            // [128][66]
    float2* Ks = smraw + 128*66;   // [128][66]
    const int z = blockIdx.z, b = z >> 4, h = z & 15;
    const float* Qb = Q + (size_t)(b*Tt)*Dd + h*DHh;   const int qstr = Dd;
    const float* Kb;  int kstr;
    if (SELF) { Kb = Kt + (size_t)(b*Tt)*Dd + h*DHh; kstr = Dd; }
    else      { Kb = Kt + (size_t)z*Tt*DHh;          kstr = DHh; }
    float* Sb = S + (size_t)z*Tt*Tt;
    const int bq = blockIdx.y*128, bk = blockIdx.x*128;
    const int tid = threadIdx.x, lane = tid&31, warp = tid>>5;
    const int wm = (warp>>2)*64, wn = (warp&3)*32;
    const int gid = lane>>2, tig = lane&3;
    const int ldr = tid>>1, ldc = (tid&1)*32;
    // load full 128x64 Q and K tiles
    #pragma unroll
    for (int i=0;i<8;i++){
        float4 qv = *(const float4*)(Qb + (size_t)(bq+ldr)*qstr + ldc + i*4);
        float4 kv = *(const float4*)(Kb + (size_t)(bk+ldr)*kstr + ldc + i*4);
        const float* q4=(const float*)&qv; const float* k4=(const float*)&kv;
        #pragma unroll
        for (int j=0;j<4;j++){
            Qs[ldr*66 + ldc + i*4 + j] = f_hilo(q4[j]);
            Ks[ldr*66 + ldc + i*4 + j] = f_hilo(k4[j]);
        }
    }
    __syncthreads();
    float c[4][4][4] = {};
    #pragma unroll
    for (int k8=0;k8<8;k8++){
        const int kb = k8*8;
        uint32_t ahi[4][4], alo[4][4], bhi[4][2], blo[4][2];
        #pragma unroll
        for (int mt=0;mt<4;mt++){
            int mb = wm + mt*16 + gid;
            float2 f0 = Qs[mb*66 + kb+tig];
            float2 f1 = Qs[(mb+8)*66 + kb+tig];
            float2 f2 = Qs[mb*66 + kb+tig+4];
            float2 f3 = Qs[(mb+8)*66 + kb+tig+4];
            ahi[mt][0]=__float_as_uint(f0.x); alo[mt][0]=__float_as_uint(f0.y);
            ahi[mt][1]=__float_as_uint(f1.x); alo[mt][1]=__float_as_uint(f1.y);
            ahi[mt][2]=__float_as_uint(f2.x); alo[mt][2]=__float_as_uint(f2.y);
            ahi[mt][3]=__float_as_uint(f3.x); alo[mt][3]=__float_as_uint(f3.y);
        }
        #pragma unroll
        for (int nt=0;nt<4;nt++){
            int nb = wn + nt*8 + gid;
            float2 g0 = Ks[nb*66 + kb+tig];
            float2 g1 = Ks[nb*66 + kb+tig+4];
            bhi[nt][0]=__float_as_uint(g0.x); blo[nt][0]=__float_as_uint(g0.y);
            bhi[nt][1]=__float_as_uint(g1.x); blo[nt][1]=__float_as_uint(g1.y);
        }
        #pragma unroll
        for (int mt=0;mt<4;mt++)
            #pragma unroll
            for (int nt=0;nt<4;nt++){
                mma8(c[mt][nt], ahi[mt], bhi[nt]);
                mma8(c[mt][nt], alo[mt], bhi[nt]);
                mma8(c[mt][nt], ahi[mt], blo[nt]);
            }
    }
    #pragma unroll
    for (int mt=0;mt<4;mt++){
        #pragma unroll
        for (int nt=0;nt<4;nt++){
            int col = bk + wn + nt*8 + tig*2;
            #pragma unroll
            for (int half=0; half<2; half++){
                int row = bq + wm + mt*16 + gid + half*8;
                float2 val = make_float2(c[mt][nt][half*2]*INV_RD,
                                         c[mt][nt][half*2+1]*INV_RD);
                *(float2*)(Sb + (size_t)row*Tt + col) = val;
            }
        }
    }
}

// ---------------- softmax over rows of S (optional causal mask) ------------
template<bool CAUSAL>
__global__ void softmax_kernel(float* __restrict__ S) {
    const int r = blockIdx.x*8 + (threadIdx.x >> 5);
    const int lane = threadIdx.x & 31;
    float4* row = (float4*)(S + (size_t)r*Tt);
    const int q = r & (Tt-1);
    const float NEG_INF = __int_as_float(0xff800000);
    float4 v[4];
    float m = -3.0e38f;
    #pragma unroll
    for (int w=0; w<4; w++){
        v[w] = row[w*32 + lane];
        if (CAUSAL){
            int c0 = (w*32 + lane)*4;
            if (c0+0 > q) v[w].x = NEG_INF;
            if (c0+1 > q) v[w].y = NEG_INF;
            if (c0+2 > q) v[w].z = NEG_INF;
            if (c0+3 > q) v[w].w = NEG_INF;
        }
        m = fmaxf(m, fmaxf(fmaxf(v[w].x,v[w].y), fmaxf(v[w].z,v[w].w)));
    }
    #pragma unroll
    for (int o=16;o;o>>=1) m = fmaxf(m, __shfl_xor_sync(0xffffffffu,m,o));
    float sum = 0.f;
    #pragma unroll
    for (int w=0; w<4; w++){
        v[w].x = __expf(v[w].x - m);
        v[w].y = __expf(v[w].y - m);
        v[w].z = __expf(v[w].z - m);
        v[w].w = __expf(v[w].w - m);
        sum += v[w].x+v[w].y+v[w].z+v[w].w;
    }
    #pragma unroll
    for (int o=16;o;o>>=1) sum += __shfl_xor_sync(0xffffffffu,sum,o);
    float inv = __frcp_rn(sum);
    #pragma unroll
    for (int w=0; w<4; w++){
        v[w].x*=inv; v[w].y*=inv; v[w].z*=inv; v[w].w*=inv;
        row[w*32 + lane] = v[w];
    }
}

// ---------------- PV (tensor cores, tf32x3): X += P @ V --------------------
// Out tile 128x64 per (q-tile, z). 8 warps (4m x 2n), warp tile 32x32.
// CLIMIT: causal — P[q][k]==0 for k>q, so stop k-loop at bq+128.
template<bool SELF, bool CLIMIT>
__global__ void __launch_bounds__(256)
pv_tc(const float* __restrict__ S, const float* __restrict__ V,
      float* __restrict__ X) {
    extern __shared__ float2 smraw[];
    float2* Ps = smraw;            // [128][34]
    float2* Vs = smraw + 128*34;   // [32][66]
    const int z = blockIdx.y, b = z >> 4, h = z & 15;
    const float* Pb = S + (size_t)z*Tt*Tt;
    const float* Vb; int vstr;
    if (SELF) { Vb = V + (size_t)(b*Tt)*Dd + h*DHh; vstr = Dd; }
    else      { Vb = V + (size_t)z*Tt*DHh;          vstr = DHh; }
    float* Xb = X + (size_t)(b*Tt)*Dd + h*DHh;
    const int bq = blockIdx.x*128;
    const int tid = threadIdx.x, lane = tid&31, warp = tid>>5;
    const int wm = (warp>>1)*32, wn = (warp&1)*32;
    const int gid = lane>>2, tig = lane&3;
    const int ldr = tid>>1, ldc = (tid&1)*16;       // P loads
    const int vr = tid>>3, vc = (tid&7)*8;          // V loads
    const int kend = CLIMIT ? (bq + 128) : Tt;
    float c[2][4][4] = {};
    float4 pv4[4], vv[2];
    #pragma unroll
    for (int i=0;i<4;i++) pv4[i] = *(const float4*)(Pb + (size_t)(bq+ldr)*Tt + ldc + i*4);
    #pragma unroll
    for (int i=0;i<2;i++) vv[i] = *(const float4*)(Vb + (size_t)vr*vstr + vc + i*4);
    for (int k0=0;k0<kend;k0+=32){
        __syncthreads();
        #pragma unroll
        for (int i=0;i<4;i++){
            const float* p4=(const float*)&pv4[i];
            #pragma unroll
            for (int j=0;j<4;j++) Ps[ldr*34 + ldc + i*4 + j] = f_hilo(p4[j]);
        }
        #pragma unroll
        for (int i=0;i<2;i++){
            const float* v4=(const float*)&vv[i];
            #pragma unroll
            for (int j=0;j<4;j++) Vs[vr*66 + vc + i*4 + j] = f_hilo(v4[j]);
        }
        __syncthreads();
        if (k0+32 < kend){
            #pragma unroll
            for (int i=0;i<4;i++)
                pv4[i] = *(const float4*)(Pb + (size_t)(bq+ldr)*Tt + k0+32 + ldc + i*4);
            #pragma unroll
            for (int i=0;i<2;i++)
                vv[i] = *(const float4*)(Vb + (size_t)(k0+32+vr)*vstr + vc + i*4);
        }
        #pragma unroll
        for (int k8=0;k8<4;k8++){
            const int kb = k8*8;
            uint32_t ahi[2][4], alo[2][4], bhi[4][2], blo[4][2];
            #pragma unroll
            for (int mt=0;mt<2;mt++){
                int mb = wm + mt*16 + gid;
                float2 f0 = Ps[mb*34 + kb+tig];
                float2 f1 = Ps[(mb+8)*34 + kb+tig];
                float2 f2 = Ps[mb*34 + kb+tig+4];
                float2 f3 = Ps[(mb+8)*34 + kb+tig+4];
                ahi[mt][0]=__float_as_uint(f0.x); alo[mt][0]=__float_as_uint(f0.y);
                ahi[mt][1]=__float_as_uint(f1.x); alo[mt][1]=__float_as_uint(f1.y);
                ahi[mt][2]=__float_as_uint(f2.x); alo[mt][2]=__float_as_uint(f2.y);
                ahi[mt][3]=__float_as_uint(f3.x); alo[mt][3]=__float_as_uint(f3.y);
            }
            #pragma unroll
            for (int nt=0;nt<4;nt++){
                int nb = wn + nt*8 + gid;
                float2 g0 = Vs[(kb+tig)*66 + nb];
                float2 g1 = Vs[(kb+tig+4)*66 + nb];
                bhi[nt][0]=__float_as_uint(g0.x); blo[nt][0]=__float_as_uint(g0.y);
                bhi[nt][1]=__float_as_uint(g1.x); blo[nt][1]=__float_as_uint(g1.y);
            }
            #pragma unroll
            for (int mt=0;mt<2;mt++)
                #pragma unroll
                for (int nt=0;nt<4;nt++){
                    mma8(c[mt][nt], ahi[mt], bhi[nt]);
                    mma8(c[mt][nt], alo[mt], bhi[nt]);
                    mma8(c[mt][nt], ahi[mt], blo[nt]);
                }
        }
    }
    #pragma unroll
    for (int mt=0;mt<2;mt++){
        #pragma unroll
        for (int nt=0;nt<4;nt++){
            int col = wn + nt*8 + tig*2;
            #pragma unroll
            for (int half=0; half<2; half++){
                int row = bq + wm + mt*16 + gid + half*8;
                float2* xp = (float2*)(Xb + (size_t)row*Dd + col);
                float2 o = *xp;
                o.x += c[mt][nt][half*2];
                o.y += c[mt][nt][half*2+1];
                *xp = o;
            }
        }
    }
}

// ---------------- ordinal sigmoid head ------------------------------------
__global__ void head_kernel(const float* __restrict__ X,
                            const float* __restrict__ cutoff,
                            float* __restrict__ out) {
    __shared__ float E[9];
    if (threadIdx.x < 9) {
        float bj = cutoff[0];
        for (int j=1;j<=threadIdx.x;j++){ float c = cutoff[j]; bj += c*c; }
        E[threadIdx.x] = __expf(-bj);
    }
    __syncthreads();
    const int n = Mrows*Dd;
    for (int idx = blockIdx.x*blockDim.x + threadIdx.x; idx < n;
         idx += gridDim.x*blockDim.x) {
        float xv = X[idx];
        float ex = __expf(xv);
        float s[9];
        #pragma unroll
        for (int j=0;j<9;j++) s[j] = __fdividef(1.0f, 1.0f + ex*E[j]);
        float2* o2 = (float2*)(out + (size_t)idx*10);
        o2[0] = make_float2(s[0],        s[1]-s[0]);
        o2[1] = make_float2(s[2]-s[1],   s[3]-s[2]);
        o2[2] = make_float2(s[4]-s[3],   s[5]-s[4]);
        o2[3] = make_float2(s[6]-s[5],   s[7]-s[6]);
        o2[4] = make_float2(s[8]-s[7],   1.0f - s[8]);
    }
}

// ---------------- launcher --------------------------------------------------
#define SM_GEMM   (2*128*34*(int)sizeof(float2))              // 69632
#define SM_SCORES (2*128*66*(int)sizeof(float2))              // 135168
#define SM_PV     ((128*34 + 32*66)*(int)sizeof(float2))      // 51712

extern "C" void kernel_launch(void* const* d_in, const int* in_sizes, int n_in,
                              void* d_out, int out_size) {
    (void)in_sizes; (void)n_in; (void)out_size;
    const float* x    = (const float*)d_in[0];
    const float* k    = (const float*)d_in[1];
    const float* v    = (const float*)d_in[2];
    const float* pos  = (const float*)d_in[3];
    const float* Wq1  = (const float*)d_in[4];
    const float* Wk1  = (const float*)d_in[5];
    const float* Wv1  = (const float*)d_in[6];
    const float* Wq2  = (const float*)d_in[7];
    const float* Wfc  = (const float*)d_in[8];
    const float* bfc  = (const float*)d_in[9];
    const float* g1   = (const float*)d_in[10];
    const float* b1   = (const float*)d_in[11];
    const float* g2   = (const float*)d_in[12];
    const float* b2   = (const float*)d_in[13];
    const float* g3   = (const float*)d_in[14];
    const float* b3   = (const float*)d_in[15];
    const float* cut  = (const float*)d_in[16];
    float* out = (float*)d_out;

    float *xa, *xb, *q, *kk, *vv, *S;
    cudaGetSymbolAddress((void**)&xa, g_xa);
    cudaGetSymbolAddress((void**)&xb, g_xb);
    cudaGetSymbolAddress((void**)&q,  g_q);
    cudaGetSymbolAddress((void**)&kk, g_k);
    cudaGetSymbolAddress((void**)&vv, g_v);
    cudaGetSymbolAddress((void**)&S,  g_s);

    // opt-in dynamic smem (idempotent; host-side, capture-safe)
    cudaFuncSetAttribute(gemm_tc<false>, cudaFuncAttributeMaxDynamicSharedMemorySize, SM_GEMM);
    cudaFuncSetAttribute(gemm_tc<true>,  cudaFuncAttributeMaxDynamicSharedMemorySize, SM_GEMM);
    cudaFuncSetAttribute(scores_tc<true,false>,  cudaFuncAttributeMaxDynamicSharedMemorySize, SM_SCORES);
    cudaFuncSetAttribute(scores_tc<false,true>,  cudaFuncAttributeMaxDynamicSharedMemorySize, SM_SCORES);
    cudaFuncSetAttribute(pv_tc<true,false>, cudaFuncAttributeMaxDynamicSharedMemorySize, SM_PV);
    cudaFuncSetAttribute(pv_tc<false,true>, cudaFuncAttributeMaxDynamicSharedMemorySize, SM_PV);

    add_pos_kernel<<<Mrows*Dd/4/256, 256>>>(x, pos, xa);

    float* cur = xa; float* oth = xb;
    const dim3 gGemm(8, 32);
    const dim3 gScores(4, 4, BH);
    const dim3 gPV(4, BH);
    const int gSoft = BH*Tt/8;

    for (int i = 0; i < Ll; i++) {
        if (i) ln_kernel<<<Mrows,256>>>(cur, g1 + (size_t)(i-1)*Dd, b1 + (size_t)(i-1)*Dd);
        // self-attention
        gemm_tc<false><<<gGemm,256,SM_GEMM>>>(cur, Wq1 + (size_t)i*Dd*Dd, nullptr, q);
        gemm_tc<false><<<gGemm,256,SM_GEMM>>>(cur, Wk1 + (size_t)i*Dd*Dd, nullptr, kk);
        gemm_tc<false><<<gGemm,256,SM_GEMM>>>(cur, Wv1 + (size_t)i*Dd*Dd, nullptr, vv);
        scores_tc<true,false><<<gScores,256,SM_SCORES>>>(q, kk, S);
        softmax_kernel<false><<<gSoft,256>>>(S);
        pv_tc<true,false><<<gPV,256,SM_PV>>>(S, vv, cur);
        ln_kernel<<<Mrows,256>>>(cur, g2 + (size_t)i*Dd, b2 + (size_t)i*Dd);
        // cross-attention (causal)
        gemm_tc<false><<<gGemm,256,SM_GEMM>>>(cur, Wq2 + (size_t)i*Dd*Dd, nullptr, q);
        scores_tc<false,true><<<gScores,256,SM_SCORES>>>(q, k, S);
        softmax_kernel<true><<<gSoft,256>>>(S);
        pv_tc<false,true><<<gPV,256,SM_PV>>>(S, v, cur);
        ln_kernel<<<Mrows,256>>>(cur, g3 + (size_t)i*Dd, b3 + (size_t)i*Dd);
        // FC + relu + residual (ping-pong to avoid read/write race)
        gemm_tc<true><<<gGemm,256,SM_GEMM>>>(cur, Wfc + (size_t)i*Dd*Dd, bfc + (size_t)i*Dd, oth);
        float* t = cur; cur = oth; oth = t;
    }

    head_kernel<<<4096,256>>>(cur, cut, out);
}

// round 11
// speedup vs baseline: 1.0000x; 1.0000x over previous
#include <cuda_runtime.h>
#include <cstdint>

// Problem constants
#define Bsz 8
#define Tt  512
#define Dd  1024
#define Hh  16
#define DHh 64
#define Ll  4
#define Cc  10
#define Mrows (Bsz*Tt)   // 4096
#define BH   (Bsz*Hh)    // 128
#define INV_RD (1.0f/32.0f)

// ---------------- scratch (static device globals: allocation-free) ----------
__device__ float g_xa[Mrows*Dd];
__device__ float g_xb[Mrows*Dd];
__device__ float g_q [Mrows*Dd];
__device__ float g_k [Mrows*Dd];
__device__ float g_v [Mrows*Dd];
__device__ float g_s [(size_t)BH*Tt*Tt];   // 134 MB scores

// ---------------- tf32x3 helpers -------------------------------------------
__device__ __forceinline__ float2 f_hilo(float f) {
    uint32_t h;
    asm("cvt.rna.tf32.f32 %0, %1;" : "=r"(h) : "f"(f));
    float hf = __uint_as_float(h);
    float r  = f - hf;
    uint32_t l;
    asm("cvt.rna.tf32.f32 %0, %1;" : "=r"(l) : "f"(r));
    return make_float2(hf, __uint_as_float(l));
}

__device__ __forceinline__ void mma8(float c[4], const uint32_t a[4], const uint32_t b[2]) {
    asm volatile("mma.sync.aligned.m16n8k8.row.col.f32.tf32.tf32.f32 "
        "{%0,%1,%2,%3}, {%4,%5,%6,%7}, {%8,%9}, {%0,%1,%2,%3};"
        : "+f"(c[0]), "+f"(c[1]), "+f"(c[2]), "+f"(c[3])
        : "r"(a[0]), "r"(a[1]), "r"(a[2]), "r"(a[3]), "r"(b[0]), "r"(b[1]));
}

// ---------------- add positional encoding ----------------------------------
__global__ void add_pos_kernel(const float* __restrict__ x,
                               const float* __restrict__ pos,
                               float* __restrict__ out) {
    int i = blockIdx.x * blockDim.x + threadIdx.x;
    const int n4 = Mrows*Dd/4;
    if (i < n4) {
        float4 a = ((const float4*)x)[i];
        float4 p = ((const float4*)pos)[i % (Tt*Dd/4)];
        a.x += p.x; a.y += p.y; a.z += p.z; a.w += p.w;
        ((float4*)out)[i] = a;
    }
}

// ---------------- layernorm (in-place, one block per row) ------------------
__global__ void ln_kernel(float* __restrict__ x,
                          const float* __restrict__ g,
                          const float* __restrict__ b) {
    __shared__ float red[16];
    __shared__ float s_mv[2];
    int row = blockIdx.x;
    int tid = threadIdx.x;
    float4* xp = (float4*)(x + (size_t)row*Dd);
    float4 v = xp[tid];
    float s  = v.x+v.y+v.z+v.w;
    float sq = v.x*v.x+v.y*v.y+v.z*v.z+v.w*v.w;
    #pragma unroll
    for (int o=16;o;o>>=1){ s += __shfl_down_sync(0xffffffffu,s,o);
                            sq += __shfl_down_sync(0xffffffffu,sq,o); }
    int warp = tid>>5, lane = tid&31;
    if (!lane){ red[warp]=s; red[8+warp]=sq; }
    __syncthreads();
    if (tid < 32){
        float a = (lane<8)? red[lane]   : 0.f;
        float c = (lane<8)? red[8+lane] : 0.f;
        #pragma unroll
        for (int o=4;o;o>>=1){ a += __shfl_down_sync(0xffffffffu,a,o);
                               c += __shfl_down_sync(0xffffffffu,c,o); }
        if (!lane){
            float mean = a * (1.0f/Dd);
            float var  = c * (1.0f/Dd) - mean*mean;
            s_mv[0] = mean;
            s_mv[1] = rsqrtf(var + 1e-5f);
        }
    }
    __syncthreads();
    float mean = s_mv[0], rstd = s_mv[1];
    float4 gg = ((const float4*)g)[tid];
    float4 bb = ((const float4*)b)[tid];
    v.x = (v.x-mean)*rstd*gg.x + bb.x;
    v.y = (v.y-mean)*rstd*gg.y + bb.y;
    v.z = (v.z-mean)*rstd*gg.z + bb.z;
    v.w = (v.w-mean)*rstd*gg.w + bb.w;
    xp[tid] = v;
}

// ---------------- projection GEMM (tensor cores, tf32x3) -------------------
// C[4096,1024] = A[4096,1024] @ W[1024,1024]^T. 128x128 block, BK=32,
// 256 threads = 8 warps (2m x 4n), warp tile 64x32 (4 m-tiles x 4 n-tiles).
// smem holds (hi,lo) float2 per element; pitch 34 to dodge bank conflicts.
template<bool FCEPI>
__global__ void __launch_bounds__(256)
gemm_tc(const float* __restrict__ A, const float* __restrict__ W,
        const float* __restrict__ bias, float* __restrict__ C) {
    extern __shared__ float2 smraw[];
    float2* As = smraw;            // [128][34]
    float2* Bs = smraw + 128*34;   // [128][34]
    const int tid = threadIdx.x, lane = tid&31, warp = tid>>5;
    const int wm = (warp>>2)*64, wn = (warp&3)*32;
    const int gid = lane>>2, tig = lane&3;
    const int bm = blockIdx.y*128, bn = blockIdx.x*128;
    const int ldr = tid>>1, ldc = (tid&1)*16;
    const float* Ap = A + (size_t)(bm+ldr)*Dd + ldc;
    const float* Wp = W + (size_t)(bn+ldr)*Dd + ldc;
    float c[4][4][4] = {};
    float4 av[4], wv[4];
    #pragma unroll
    for (int i=0;i<4;i++){ av[i] = *(const float4*)(Ap + i*4);
                           wv[i] = *(const float4*)(Wp + i*4); }
    for (int k0=0;k0<Dd;k0+=32){
        __syncthreads();
        #pragma unroll
        for (int i=0;i<4;i++){
            const float* a4=(const float*)&av[i];
            const float* w4=(const float*)&wv[i];
            #pragma unroll
            for(int j=0;j<4;j++){
                As[ldr*34 + ldc + i*4 + j] = f_hilo(a4[j]);
                Bs[ldr*34 + ldc + i*4 + j] = f_hilo(w4[j]);
            }
        }
        __syncthreads();
        if (k0+32 < Dd){
            #pragma unroll
            for (int i=0;i<4;i++){ av[i] = *(const float4*)(Ap + k0+32 + i*4);
                                   wv[i] = *(const float4*)(Wp + k0+32 + i*4); }
        }
        #pragma unroll
        for (int k8=0;k8<4;k8++){
            const int kb = k8*8;
            uint32_t ahi[4][4], alo[4][4], bhi[4][2], blo[4][2];
            #pragma unroll
            for (int mt=0;mt<4;mt++){
                int mb = wm + mt*16 + gid;
                float2 f0 = As[mb*34 + kb+tig];
                float2 f1 = As[(mb+8)*34 + kb+tig];
                float2 f2 = As[mb*34 + kb+tig+4];
                float2 f3 = As[(mb+8)*34 + kb+tig+4];
                ahi[mt][0]=__float_as_uint(f0.x); alo[mt][0]=__float_as_uint(f0.y);
                ahi[mt][1]=__float_as_uint(f1.x); alo[mt][1]=__float_as_uint(f1.y);
                ahi[mt][2]=__float_as_uint(f2.x); alo[mt][2]=__float_as_uint(f2.y);
                ahi[mt][3]=__float_as_uint(f3.x); alo[mt][3]=__float_as_uint(f3.y);
            }
            #pragma unroll
            for (int nt=0;nt<4;nt++){
                int nb = wn + nt*8 + gid;
                float2 g0 = Bs[nb*34 + kb+tig];
                float2 g1 = Bs[nb*34 + kb+tig+4];
                bhi[nt][0]=__float_as_uint(g0.x); blo[nt][0]=__float_as_uint(g0.y);
                bhi[nt][1]=__float_as_uint(g1.x); blo[nt][1]=__float_as_uint(g1.y);
            }
            #pragma unroll
            for (int mt=0;mt<4;mt++)
                #pragma unroll
                for (int nt=0;nt<4;nt++){
                    mma8(c[mt][nt], ahi[mt], bhi[nt]);
                    mma8(c[mt][nt], alo[mt], bhi[nt]);
                    mma8(c[mt][nt], ahi[mt], blo[nt]);
                }
        }
    }
    #pragma unroll
    for (int mt=0;mt<4;mt++){
        #pragma unroll
        for (int nt=0;nt<4;nt++){
            int col = bn + wn + nt*8 + tig*2;
            #pragma unroll
            for (int half=0; half<2; half++){
                int row = bm + wm + mt*16 + gid + half*8;
                float2 val = make_float2(c[mt][nt][half*2], c[mt][nt][half*2+1]);
                if (FCEPI){
                    float2 bi = *(const float2*)(bias + col);
                    float2 r  = *(const float2*)(A + (size_t)row*Dd + col);
                    val.x = fmaxf(val.x+bi.x, 0.f) + r.x;
                    val.y = fmaxf(val.y+bi.y, 0.f) + r.y;
                }
                *(float2*)(C + (size_t)row*Dd + col) = val;
            }
        }
    }
}

// ---------------- attention scores (tensor cores, tf32x3) ------------------
// S[z,q,k] = (Q[q]·K[k])/32.  128x128 tile, K-dim=64 loaded in one shot.
// CSKIP: skip fully-masked causal tiles (bk tile strictly above bq tile).
template<bool SELF, bool CSKIP>
__global__ void __launch_bounds__(256)
scores_tc(const float* __restrict__ Q, const float* __restrict__ Kt,
          float* __restrict__ S) {
    if (CSKIP && blockIdx.x > blockIdx.y) return;
    extern __shared__ float2 smraw[];
    float2* Qs = smraw;            // [128][66]
    float2* Ks = smraw + 128*66;   // [128][66]
    const int z = blockIdx.z, b = z >> 4, h = z & 15;
    const float* Qb = Q + (size_t)(b*Tt)*Dd + h*DHh;   const int qstr = Dd;
    const float* Kb;  int kstr;
    if (SELF) { Kb = Kt + (size_t)(b*Tt)*Dd + h*DHh; kstr = Dd; }
    else      { Kb = Kt + (size_t)z*Tt*DHh;          kstr = DHh; }
    float* Sb = S + (size_t)z*Tt*Tt;
    const int bq = blockIdx.y*128, bk = blockIdx.x*128;
    const int tid = threadIdx.x, lane = tid&31, warp = tid>>5;
    const int wm = (warp>>2)*64, wn = (warp&3)*32;
    const int gid = lane>>2, tig = lane&3;
    const int ldr = tid>>1, ldc = (tid&1)*32;
    // load full 128x64 Q and K tiles
    #pragma unroll
    for (int i=0;i<8;i++){
        float4 qv = *(const float4*)(Qb + (size_t)(bq+ldr)*qstr + ldc + i*4);
        float4 kv = *(const float4*)(Kb + (size_t)(bk+ldr)*kstr + ldc + i*4);
        const float* q4=(const float*)&qv; const float* k4=(const float*)&kv;
        #pragma unroll
        for (int j=0;j<4;j++){
            Qs[ldr*66 + ldc + i*4 + j] = f_hilo(q4[j]);
            Ks[ldr*66 + ldc + i*4 + j] = f_hilo(k4[j]);
        }
    }
    __syncthreads();
    float c[4][4][4] = {};
    #pragma unroll
    for (int k8=0;k8<8;k8++){
        const int kb = k8*8;
        uint32_t ahi[4][4], alo[4][4], bhi[4][2], blo[4][2];
        #pragma unroll
        for (int mt=0;mt<4;mt++){
            int mb = wm + mt*16 + gid;
            float2 f0 = Qs[mb*66 + kb+tig];
            float2 f1 = Qs[(mb+8)*66 + kb+tig];
            float2 f2 = Qs[mb*66 + kb+tig+4];
            float2 f3 = Qs[(mb+8)*66 + kb+tig+4];
            ahi[mt][0]=__float_as_uint(f0.x); alo[mt][0]=__float_as_uint(f0.y);
            ahi[mt][1]=__float_as_uint(f1.x); alo[mt][1]=__float_as_uint(f1.y);
            ahi[mt][2]=__float_as_uint(f2.x); alo[mt][2]=__float_as_uint(f2.y);
            ahi[mt][3]=__float_as_uint(f3.x); alo[mt][3]=__float_as_uint(f3.y);
        }
        #pragma unroll
        for (int nt=0;nt<4;nt++){
            int nb = wn + nt*8 + gid;
            float2 g0 = Ks[nb*66 + kb+tig];
            float2 g1 = Ks[nb*66 + kb+tig+4];
            bhi[nt][0]=__float_as_uint(g0.x); blo[nt][0]=__float_as_uint(g0.y);
            bhi[nt][1]=__float_as_uint(g1.x); blo[nt][1]=__float_as_uint(g1.y);
        }
        #pragma unroll
        for (int mt=0;mt<4;mt++)
            #pragma unroll
            for (int nt=0;nt<4;nt++){
                mma8(c[mt][nt], ahi[mt], bhi[nt]);
                mma8(c[mt][nt], alo[mt], bhi[nt]);
                mma8(c[mt][nt], ahi[mt], blo[nt]);
            }
    }
    #pragma unroll
    for (int mt=0;mt<4;mt++){
        #pragma unroll
        for (int nt=0;nt<4;nt++){
            int col = bk + wn + nt*8 + tig*2;
            #pragma unroll
            for (int half=0; half<2; half++){
                int row = bq + wm + mt*16 + gid + half*8;
                float2 val = make_float2(c[mt][nt][half*2]*INV_RD,
                                         c[mt][nt][half*2+1]*INV_RD);
                *(float2*)(Sb + (size_t)row*Tt + col) = val;
            }
        }
    }
}

// ---------------- softmax over rows of S (optional causal mask) ------------
template<bool CAUSAL>
__global__ void softmax_kernel(float* __restrict__ S) {
    const int r = blockIdx.x*8 + (threadIdx.x >> 5);
    const int lane = threadIdx.x & 31;
    float4* row = (float4*)(S + (size_t)r*Tt);
    const int q = r & (Tt-1);
    const float NEG_INF = __int_as_float(0xff800000);
    float4 v[4];
    float m = -3.0e38f;
    #pragma unroll
    for (int w=0; w<4; w++){
        v[w] = row[w*32 + lane];
        if (CAUSAL){
            int c0 = (w*32 + lane)*4;
            if (c0+0 > q) v[w].x = NEG_INF;
            if (c0+1 > q) v[w].y = NEG_INF;
            if (c0+2 > q) v[w].z = NEG_INF;
            if (c0+3 > q) v[w].w = NEG_INF;
        }
        m = fmaxf(m, fmaxf(fmaxf(v[w].x,v[w].y), fmaxf(v[w].z,v[w].w)));
    }
    #pragma unroll
    for (int o=16;o;o>>=1) m = fmaxf(m, __shfl_xor_sync(0xffffffffu,m,o));
    float sum = 0.f;
    #pragma unroll
    for (int w=0; w<4; w++){
        v[w].x = __expf(v[w].x - m);
        v[w].y = __expf(v[w].y - m);
        v[w].z = __expf(v[w].z - m);
        v[w].w = __expf(v[w].w - m);
        sum += v[w].x+v[w].y+v[w].z+v[w].w;
    }
    #pragma unroll
    for (int o=16;o;o>>=1) sum += __shfl_xor_sync(0xffffffffu,sum,o);
    float inv = __frcp_rn(sum);
    #pragma unroll
    for (int w=0; w<4; w++){
        v[w].x*=inv; v[w].y*=inv; v[w].z*=inv; v[w].w*=inv;
        row[w*32 + lane] = v[w];
    }
}

// ---------------- PV (tensor cores, tf32x3): X += P @ V --------------------
// Out tile 128x64 per (q-tile, z). 8 warps (4m x 2n), warp tile 32x32.
// CLIMIT: causal — P[q][k]==0 for k>q, so stop k-loop at bq+128.
template<bool SELF, bool CLIMIT>
__global__ void __launch_bounds__(256)
pv_tc(const float* __restrict__ S, const float* __restrict__ V,
      float* __restrict__ X) {
    extern __shared__ float2 smraw[];
    float2* Ps = smraw;            // [128][34]
    float2* Vs = smraw + 128*34;   // [32][66]
    const int z = blockIdx.y, b = z >> 4, h = z & 15;
    const float* Pb = S + (size_t)z*Tt*Tt;
    const float* Vb; int vstr;
    if (SELF) { Vb = V + (size_t)(b*Tt)*Dd + h*DHh; vstr = Dd; }
    else      { Vb = V + (size_t)z*Tt*DHh;          vstr = DHh; }
    float* Xb = X + (size_t)(b*Tt)*Dd + h*DHh;
    const int bq = blockIdx.x*128;
    const int tid = threadIdx.x, lane = tid&31, warp = tid>>5;
    const int wm = (warp>>1)*32, wn = (warp&1)*32;
    const int gid = lane>>2, tig = lane&3;
    const int ldr = tid>>1, ldc = (tid&1)*16;       // P loads
    const int vr = tid>>3, vc = (tid&7)*8;          // V loads
    const int kend = CLIMIT ? (bq + 128) : Tt;
    float c[2][4][4] = {};
    float4 pv4[4], vv[2];
    #pragma unroll
    for (int i=0;i<4;i++) pv4[i] = *(const float4*)(Pb + (size_t)(bq+ldr)*Tt + ldc + i*4);
    #pragma unroll
    for (int i=0;i<2;i++) vv[i] = *(const float4*)(Vb + (size_t)vr*vstr + vc + i*4);
    for (int k0=0;k0<kend;k0+=32){
        __syncthreads();
        #pragma unroll
        for (int i=0;i<4;i++){
            const float* p4=(const float*)&pv4[i];
            #pragma unroll
            for (int j=0;j<4;j++) Ps[ldr*34 + ldc + i*4 + j] = f_hilo(p4[j]);
        }
        #pragma unroll
        for (int i=0;i<2;i++){
            const float* v4=(const float*)&vv[i];
            #pragma unroll
            for (int j=0;j<4;j++) Vs[vr*66 + vc + i*4 + j] = f_hilo(v4[j]);
        }
        __syncthreads();
        if (k0+32 < kend){
            #pragma unroll
            for (int i=0;i<4;i++)
                pv4[i] = *(const float4*)(Pb + (size_t)(bq+ldr)*Tt + k0+32 + ldc + i*4);
            #pragma unroll
            for (int i=0;i<2;i++)
                vv[i] = *(const float4*)(Vb + (size_t)(k0+32+vr)*vstr + vc + i*4);
        }
        #pragma unroll
        for (int k8=0;k8<4;k8++){
            const int kb = k8*8;
            uint32_t ahi[2][4], alo[2][4], bhi[4][2], blo[4][2];
            #pragma unroll
            for (int mt=0;mt<2;mt++){
                int mb = wm + mt*16 + gid;
                float2 f0 = Ps[mb*34 + kb+tig];
                float2 f1 = Ps[(mb+8)*34 + kb+tig];
                float2 f2 = Ps[mb*34 + kb+tig+4];
                float2 f3 = Ps[(mb+8)*34 + kb+tig+4];
                ahi[mt][0]=__float_as_uint(f0.x); alo[mt][0]=__float_as_uint(f0.y);
                ahi[mt][1]=__float_as_uint(f1.x); alo[mt][1]=__float_as_uint(f1.y);
                ahi[mt][2]=__float_as_uint(f2.x); alo[mt][2]=__float_as_uint(f2.y);
                ahi[mt][3]=__float_as_uint(f3.x); alo[mt][3]=__float_as_uint(f3.y);
            }
            #pragma unroll
            for (int nt=0;nt<4;nt++){
                int nb = wn + nt*8 + gid;
                float2 g0 = Vs[(kb+tig)*66 + nb];
                float2 g1 = Vs[(kb+tig+4)*66 + nb];
                bhi[nt][0]=__float_as_uint(g0.x); blo[nt][0]=__float_as_uint(g0.y);
                bhi[nt][1]=__float_as_uint(g1.x); blo[nt][1]=__float_as_uint(g1.y);
            }
            #pragma unroll
            for (int mt=0;mt<2;mt++)
                #pragma unroll
                for (int nt=0;nt<4;nt++){
                    mma8(c[mt][nt], ahi[mt], bhi[nt]);
                    mma8(c[mt][nt], alo[mt], bhi[nt]);
                    mma8(c[mt][nt], ahi[mt], blo[nt]);
                }
        }
    }
    #pragma unroll
    for (int mt=0;mt<2;mt++){
        #pragma unroll
        for (int nt=0;nt<4;nt++){
            int col = wn + nt*8 + tig*2;
            #pragma unroll
            for (int half=0; half<2; half++){
                int row = bq + wm + mt*16 + gid + half*8;
                float2* xp = (float2*)(Xb + (size_t)row*Dd + col);
                float2 o = *xp;
                o.x += c[mt][nt][half*2];
                o.y += c[mt][nt][half*2+1];
                *xp = o;
            }
        }
    }
}

// ---------------- ordinal sigmoid head ------------------------------------
__global__ void head_kernel(const float* __restrict__ X,
                            const float* __restrict__ cutoff,
                            float* __restrict__ out) {
    __shared__ float E[9];
    if (threadIdx.x < 9) {
        float bj = cutoff[0];
        for (int j=1;j<=threadIdx.x;j++){ float c = cutoff[j]; bj += c*c; }
        E[threadIdx.x] = __expf(-bj);
    }
    __syncthreads();
    const int n = Mrows*Dd;
    for (int idx = blockIdx.x*blockDim.x + threadIdx.x; idx < n;
         idx += gridDim.x*blockDim.x) {
        float xv = X[idx];
        float ex = __expf(xv);
        float s[9];
        #pragma unroll
        for (int j=0;j<9;j++) s[j] = __fdividef(1.0f, 1.0f + ex*E[j]);
        float2* o2 = (float2*)(out + (size_t)idx*10);
        o2[0] = make_float2(s[0],        s[1]-s[0]);
        o2[1] = make_float2(s[2]-s[1],   s[3]-s[2]);
        o2[2] = make_float2(s[4]-s[3],   s[5]-s[4]);
        o2[3] = make_float2(s[6]-s[5],   s[7]-s[6]);
        o2[4] = make_float2(s[8]-s[7],   1.0f - s[8]);
    }
}

// ---------------- launcher --------------------------------------------------
#define SM_GEMM   (2*128*34*(int)sizeof(float2))              // 69632
#define SM_SCORES (2*128*66*(int)sizeof(float2))              // 135168
#define SM_PV     ((128*34 + 32*66)*(int)sizeof(float2))      // 51712

extern "C" void kernel_launch(void* const* d_in, const int* in_sizes, int n_in,
                              void* d_out, int out_size) {
    (void)in_sizes; (void)n_in; (void)out_size;
    const float* x    = (const float*)d_in[0];
    const float* k    = (const float*)d_in[1];
    const float* v    = (const float*)d_in[2];
    const float* pos  = (const float*)d_in[3];
    const float* Wq1  = (const float*)d_in[4];
    const float* Wk1  = (const float*)d_in[5];
    const float* Wv1  = (const float*)d_in[6];
    const float* Wq2  = (const float*)d_in[7];
    const float* Wfc  = (const float*)d_in[8];
    const float* bfc  = (const float*)d_in[9];
    const float* g1   = (const float*)d_in[10];
    const float* b1   = (const float*)d_in[11];
    const float* g2   = (const float*)d_in[12];
    const float* b2   = (const float*)d_in[13];
    const float* g3   = (const float*)d_in[14];
    const float* b3   = (const float*)d_in[15];
    const float* cut  = (const float*)d_in[16];
    float* out = (float*)d_out;

    float *xa, *xb, *q, *kk, *vv, *S;
    cudaGetSymbolAddress((void**)&xa, g_xa);
    cudaGetSymbolAddress((void**)&xb, g_xb);
    cudaGetSymbolAddress((void**)&q,  g_q);
    cudaGetSymbolAddress((void**)&kk, g_k);
    cudaGetSymbolAddress((void**)&vv, g_v);
    cudaGetSymbolAddress((void**)&S,  g_s);

    // opt-in dynamic smem (idempotent; host-side, capture-safe)
    cudaFuncSetAttribute(gemm_tc<false>, cudaFuncAttributeMaxDynamicSharedMemorySize, SM_GEMM);
    cudaFuncSetAttribute(gemm_tc<true>,  cudaFuncAttributeMaxDynamicSharedMemorySize, SM_GEMM);
    cudaFuncSetAttribute(scores_tc<true,false>,  cudaFuncAttributeMaxDynamicSharedMemorySize, SM_SCORES);
    cudaFuncSetAttribute(scores_tc<false,true>,  cudaFuncAttributeMaxDynamicSharedMemorySize, SM_SCORES);
    cudaFuncSetAttribute(pv_tc<true,false>, cudaFuncAttributeMaxDynamicSharedMemorySize, SM_PV);
    cudaFuncSetAttribute(pv_tc<false,true>, cudaFuncAttributeMaxDynamicSharedMemorySize, SM_PV);

    add_pos_kernel<<<Mrows*Dd/4/256, 256>>>(x, pos, xa);

    float* cur = xa; float* oth = xb;
    const dim3 gGemm(8, 32);
    const dim3 gScores(4, 4, BH);
    const dim3 gPV(4, BH);
    const int gSoft = BH*Tt/8;

    for (int i = 0; i < Ll; i++) {
        if (i) ln_kernel<<<Mrows,256>>>(cur, g1 + (size_t)(i-1)*Dd, b1 + (size_t)(i-1)*Dd);
        // self-attention
        gemm_tc<false><<<gGemm,256,SM_GEMM>>>(cur, Wq1 + (size_t)i*Dd*Dd, nullptr, q);
        gemm_tc<false><<<gGemm,256,SM_GEMM>>>(cur, Wk1 + (size_t)i*Dd*Dd, nullptr, kk);
        gemm_tc<false><<<gGemm,256,SM_GEMM>>>(cur, Wv1 + (size_t)i*Dd*Dd, nullptr, vv);
        scores_tc<true,false><<<gScores,256,SM_SCORES>>>(q, kk, S);
        softmax_kernel<false><<<gSoft,256>>>(S);
        pv_tc<true,false><<<gPV,256,SM_PV>>>(S, vv, cur);
        ln_kernel<<<Mrows,256>>>(cur, g2 + (size_t)i*Dd, b2 + (size_t)i*Dd);
        // cross-attention (causal)
        gemm_tc<false><<<gGemm,256,SM_GEMM>>>(cur, Wq2 + (size_t)i*Dd*Dd, nullptr, q);
        scores_tc<false,true><<<gScores,256,SM_SCORES>>>(q, k, S);
        softmax_kernel<true><<<gSoft,256>>>(S);
        pv_tc<false,true><<<gPV,256,SM_PV>>>(S, v, cur);
        ln_kernel<<<Mrows,256>>>(cur, g3 + (size_t)i*Dd, b3 + (size_t)i*Dd);
        // FC + relu + residual (ping-pong to avoid read/write race)
        gemm_tc<true><<<gGemm,256,SM_GEMM>>>(cur, Wfc + (size_t)i*Dd*Dd, bfc + (size_t)i*Dd, oth);
        float* t = cur; cur = oth; oth = t;
    }

    head_kernel<<<4096,256>>>(cur, cut, out);
}

// round 12
// speedup vs baseline: 1.0014x; 1.0014x over previous
#include <cuda_runtime.h>
#include <cstdint>

// Problem constants
#define Bsz 8
#define Tt  512
#define Dd  1024
#define Hh  16
#define DHh 64
#define Ll  4
#define Cc  10
#define Mrows (Bsz*Tt)   // 4096
#define BH   (Bsz*Hh)    // 128
#define INV_RD (1.0f/32.0f)

// ---------------- scratch (static device globals: allocation-free) ----------
__device__ float g_xa[Mrows*Dd];
__device__ float g_xb[Mrows*Dd];
__device__ float g_q [Mrows*Dd];
__device__ float g_k [Mrows*Dd];
__device__ float g_v [Mrows*Dd];
__device__ float g_s [(size_t)BH*Tt*Tt];   // 134 MB scores

// ---------------- tf32x3 helpers -------------------------------------------
__device__ __forceinline__ float2 f_hilo(float f) {
    uint32_t h;
    asm("cvt.rna.tf32.f32 %0, %1;" : "=r"(h) : "f"(f));
    float hf = __uint_as_float(h);
    float r  = f - hf;
    uint32_t l;
    asm("cvt.rna.tf32.f32 %0, %1;" : "=r"(l) : "f"(r));
    return make_float2(hf, __uint_as_float(l));
}

__device__ __forceinline__ void mma8(float c[4], const uint32_t a[4], const uint32_t b[2]) {
    asm volatile("mma.sync.aligned.m16n8k8.row.col.f32.tf32.tf32.f32 "
        "{%0,%1,%2,%3}, {%4,%5,%6,%7}, {%8,%9}, {%0,%1,%2,%3};"
        : "+f"(c[0]), "+f"(c[1]), "+f"(c[2]), "+f"(c[3])
        : "r"(a[0]), "r"(a[1]), "r"(a[2]), "r"(a[3]), "r"(b[0]), "r"(b[1]));
}

// ---------------- add positional encoding ----------------------------------
__global__ void add_pos_kernel(const float* __restrict__ x,
                               const float* __restrict__ pos,
                               float* __restrict__ out) {
    int i = blockIdx.x * blockDim.x + threadIdx.x;
    const int n4 = Mrows*Dd/4;
    if (i < n4) {
        float4 a = ((const float4*)x)[i];
        float4 p = ((const float4*)pos)[i % (Tt*Dd/4)];
        a.x += p.x; a.y += p.y; a.z += p.z; a.w += p.w;
        ((float4*)out)[i] = a;
    }
}

// ---------------- layernorm (in-place, one block per row) ------------------
__global__ void ln_kernel(float* __restrict__ x,
                          const float* __restrict__ g,
                          const float* __restrict__ b) {
    __shared__ float red[16];
    __shared__ float s_mv[2];
    int row = blockIdx.x;
    int tid = threadIdx.x;
    float4* xp = (float4*)(x + (size_t)row*Dd);
    float4 v = xp[tid];
    float s  = v.x+v.y+v.z+v.w;
    float sq = v.x*v.x+v.y*v.y+v.z*v.z+v.w*v.w;
    #pragma unroll
    for (int o=16;o;o>>=1){ s += __shfl_down_sync(0xffffffffu,s,o);
                            sq += __shfl_down_sync(0xffffffffu,sq,o); }
    int warp = tid>>5, lane = tid&31;
    if (!lane){ red[warp]=s; red[8+warp]=sq; }
    __syncthreads();
    if (tid < 32){
        float a = (lane<8)? red[lane]   : 0.f;
        float c = (lane<8)? red[8+lane] : 0.f;
        #pragma unroll
        for (int o=4;o;o>>=1){ a += __shfl_down_sync(0xffffffffu,a,o);
                               c += __shfl_down_sync(0xffffffffu,c,o); }
        if (!lane){
            float mean = a * (1.0f/Dd);
            float var  = c * (1.0f/Dd) - mean*mean;
            s_mv[0] = mean;
            s_mv[1] = rsqrtf(var + 1e-5f);
        }
    }
    __syncthreads();
    float mean = s_mv[0], rstd = s_mv[1];
    float4 gg = ((const float4*)g)[tid];
    float4 bb = ((const float4*)b)[tid];
    v.x = (v.x-mean)*rstd*gg.x + bb.x;
    v.y = (v.y-mean)*rstd*gg.y + bb.y;
    v.z = (v.z-mean)*rstd*gg.z + bb.z;
    v.w = (v.w-mean)*rstd*gg.w + bb.w;
    xp[tid] = v;
}

// ---------------- projection GEMM (tensor cores, tf32x3) -------------------
// C[4096,1024] = A[4096,1024] @ W[1024,1024]^T. 128x128 block, BK=32,
// 256 threads = 8 warps (2m x 4n), warp tile 64x32 (4 m-tiles x 4 n-tiles).
// smem holds (hi,lo) float2 per element; pitch 34 to dodge bank conflicts.
template<bool FCEPI>
__global__ void __launch_bounds__(256)
gemm_tc(const float* __restrict__ A, const float* __restrict__ W,
        const float* __restrict__ bias, float* __restrict__ C) {
    extern __shared__ float2 smraw[];
    float2* As = smraw;            // [128][34]
    float2* Bs = smraw + 128*34;   // [128][34]
    const int tid = threadIdx.x, lane = tid&31, warp = tid>>5;
    const int wm = (warp>>2)*64, wn = (warp&3)*32;
    const int gid = lane>>2, tig = lane&3;
    const int bm = blockIdx.y*128, bn = blockIdx.x*128;
    const int ldr = tid>>1, ldc = (tid&1)*16;
    const float* Ap = A + (size_t)(bm+ldr)*Dd + ldc;
    const float* Wp = W + (size_t)(bn+ldr)*Dd + ldc;
    float c[4][4][4] = {};
    float4 av[4], wv[4];
    #pragma unroll
    for (int i=0;i<4;i++){ av[i] = *(const float4*)(Ap + i*4);
                           wv[i] = *(const float4*)(Wp + i*4); }
    for (int k0=0;k0<Dd;k0+=32){
        __syncthreads();
        #pragma unroll
        for (int i=0;i<4;i++){
            const float* a4=(const float*)&av[i];
            const float* w4=(const float*)&wv[i];
            #pragma unroll
            for(int j=0;j<4;j++){
                As[ldr*34 + ldc + i*4 + j] = f_hilo(a4[j]);
                Bs[ldr*34 + ldc + i*4 + j] = f_hilo(w4[j]);
            }
        }
        __syncthreads();
        if (k0+32 < Dd){
            #pragma unroll
            for (int i=0;i<4;i++){ av[i] = *(const float4*)(Ap + k0+32 + i*4);
                                   wv[i] = *(const float4*)(Wp + k0+32 + i*4); }
        }
        #pragma unroll
        for (int k8=0;k8<4;k8++){
            const int kb = k8*8;
            uint32_t ahi[4][4], alo[4][4], bhi[4][2], blo[4][2];
            #pragma unroll
            for (int mt=0;mt<4;mt++){
                int mb = wm + mt*16 + gid;
                float2 f0 = As[mb*34 + kb+tig];
                float2 f1 = As[(mb+8)*34 + kb+tig];
                float2 f2 = As[mb*34 + kb+tig+4];
                float2 f3 = As[(mb+8)*34 + kb+tig+4];
                ahi[mt][0]=__float_as_uint(f0.x); alo[mt][0]=__float_as_uint(f0.y);
                ahi[mt][1]=__float_as_uint(f1.x); alo[mt][1]=__float_as_uint(f1.y);
                ahi[mt][2]=__float_as_uint(f2.x); alo[mt][2]=__float_as_uint(f2.y);
                ahi[mt][3]=__float_as_uint(f3.x); alo[mt][3]=__float_as_uint(f3.y);
            }
            #pragma unroll
            for (int nt=0;nt<4;nt++){
                int nb = wn + nt*8 + gid;
                float2 g0 = Bs[nb*34 + kb+tig];
                float2 g1 = Bs[nb*34 + kb+tig+4];
                bhi[nt][0]=__float_as_uint(g0.x); blo[nt][0]=__float_as_uint(g0.y);
                bhi[nt][1]=__float_as_uint(g1.x); blo[nt][1]=__float_as_uint(g1.y);
            }
            #pragma unroll
            for (int mt=0;mt<4;mt++)
                #pragma unroll
                for (int nt=0;nt<4;nt++){
                    mma8(c[mt][nt], ahi[mt], bhi[nt]);
                    mma8(c[mt][nt], alo[mt], bhi[nt]);
                    mma8(c[mt][nt], ahi[mt], blo[nt]);
                }
        }
    }
    #pragma unroll
    for (int mt=0;mt<4;mt++){
        #pragma unroll
        for (int nt=0;nt<4;nt++){
            int col = bn + wn + nt*8 + tig*2;
            #pragma unroll
            for (int half=0; half<2; half++){
                int row = bm + wm + mt*16 + gid + half*8;
                float2 val = make_float2(c[mt][nt][half*2], c[mt][nt][half*2+1]);
                if (FCEPI){
                    float2 bi = *(const float2*)(bias + col);
                    float2 r  = *(const float2*)(A + (size_t)row*Dd + col);
                    val.x = fmaxf(val.x+bi.x, 0.f) + r.x;
                    val.y = fmaxf(val.y+bi.y, 0.f) + r.y;
                }
                *(float2*)(C + (size_t)row*Dd + col) = val;
            }
        }
    }
}

// ---------------- attention scores (tensor cores, tf32x3) ------------------
// S[z,q,k] = (Q[q]·K[k])/32.  128x128 tile, K-dim=64 loaded in one shot.
// CSKIP: skip fully-masked causal tiles (bk tile strictly above bq tile).
template<bool SELF, bool CSKIP>
__global__ void __launch_bounds__(256)
scores_tc(const float* __restrict__ Q, const float* __restrict__ Kt,
          float* __restrict__ S) {
    if (CSKIP && blockIdx.x > blockIdx.y) return;
    extern __shared__ float2 smraw[];
    float2* Qs = smraw;            // [128][66]
    float2* Ks = smraw + 128*66;   // [128][66]
    const int z = blockIdx.z, b = z >> 4, h = z & 15;
    const float* Qb = Q + (size_t)(b*Tt)*Dd + h*DHh;   const int qstr = Dd;
    const float* Kb;  int kstr;
    if (SELF) { Kb = Kt + (size_t)(b*Tt)*Dd + h*DHh; kstr = Dd; }
    else      { Kb = Kt + (size_t)z*Tt*DHh;          kstr = DHh; }
    float* Sb = S + (size_t)z*Tt*Tt;
    const int bq = blockIdx.y*128, bk = blockIdx.x*128;
    const int tid = threadIdx.x, lane = tid&31, warp = tid>>5;
    const int wm = (warp>>2)*64, wn = (warp&3)*32;
    const int gid = lane>>2, tig = lane&3;
    const int ldr = tid>>1, ldc = (tid&1)*32;
    // load full 128x64 Q and K tiles
    #pragma unroll
    for (int i=0;i<8;i++){
        float4 qv = *(const float4*)(Qb + (size_t)(bq+ldr)*qstr + ldc + i*4);
        float4 kv = *(const float4*)(Kb + (size_t)(bk+ldr)*kstr + ldc + i*4);
        const float* q4=(const float*)&qv; const float* k4=(const float*)&kv;
        #pragma unroll
        for (int j=0;j<4;j++){
            Qs[ldr*66 + ldc + i*4 + j] = f_hilo(q4[j]);
            Ks[ldr*66 + ldc + i*4 + j] = f_hilo(k4[j]);
        }
    }
    __syncthreads();
    float c[4][4][4] = {};
    #pragma unroll
    for (int k8=0;k8<8;k8++){
        const int kb = k8*8;
        uint32_t ahi[4][4], alo[4][4], bhi[4][2], blo[4][2];
        #pragma unroll
        for (int mt=0;mt<4;mt++){
            int mb = wm + mt*16 + gid;
            float2 f0 = Qs[mb*66 + kb+tig];
            float2 f1 = Qs[(mb+8)*66 + kb+tig];
            float2 f2 = Qs[mb*66 + kb+tig+4];
            float2 f3 = Qs[(mb+8)*66 + kb+tig+4];
            ahi[mt][0]=__float_as_uint(f0.x); alo[mt][0]=__float_as_uint(f0.y);
            ahi[mt][1]=__float_as_uint(f1.x); alo[mt][1]=__float_as_uint(f1.y);
            ahi[mt][2]=__float_as_uint(f2.x); alo[mt][2]=__float_as_uint(f2.y);
            ahi[mt][3]=__float_as_uint(f3.x); alo[mt][3]=__float_as_uint(f3.y);
        }
        #pragma unroll
        for (int nt=0;nt<4;nt++){
            int nb = wn + nt*8 + gid;
            float2 g0 = Ks[nb*66 + kb+tig];
            float2 g1 = Ks[nb*66 + kb+tig+4];
            bhi[nt][0]=__float_as_uint(g0.x); blo[nt][0]=__float_as_uint(g0.y);
            bhi[nt][1]=__float_as_uint(g1.x); blo[nt][1]=__float_as_uint(g1.y);
        }
        #pragma unroll
        for (int mt=0;mt<4;mt++)
            #pragma unroll
            for (int nt=0;nt<4;nt++){
                mma8(c[mt][nt], ahi[mt], bhi[nt]);
                mma8(c[mt][nt], alo[mt], bhi[nt]);
                mma8(c[mt][nt], ahi[mt], blo[nt]);
            }
    }
    #pragma unroll
    for (int mt=0;mt<4;mt++){
        #pragma unroll
        for (int nt=0;nt<4;nt++){
            int col = bk + wn + nt*8 + tig*2;
            #pragma unroll
            for (int half=0; half<2; half++){
                int row = bq + wm + mt*16 + gid + half*8;
                float2 val = make_float2(c[mt][nt][half*2]*INV_RD,
                                         c[mt][nt][half*2+1]*INV_RD);
                *(float2*)(Sb + (size_t)row*Tt + col) = val;
            }
        }
    }
}

// ---------------- softmax over rows of S (optional causal mask) ------------
template<bool CAUSAL>
__global__ void softmax_kernel(float* __restrict__ S) {
    const int r = blockIdx.x*8 + (threadIdx.x >> 5);
    const int lane = threadIdx.x & 31;
    float4* row = (float4*)(S + (size_t)r*Tt);
    const int q = r & (Tt-1);
    const float NEG_INF = __int_as_float(0xff800000);
    float4 v[4];
    float m = -3.0e38f;
    #pragma unroll
    for (int w=0; w<4; w++){
        v[w] = row[w*32 + lane];
        if (CAUSAL){
            int c0 = (w*32 + lane)*4;
            if (c0+0 > q) v[w].x = NEG_INF;
            if (c0+1 > q) v[w].y = NEG_INF;
            if (c0+2 > q) v[w].z = NEG_INF;
            if (c0+3 > q) v[w].w = NEG_INF;
        }
        m = fmaxf(m, fmaxf(fmaxf(v[w].x,v[w].y), fmaxf(v[w].z,v[w].w)));
    }
    #pragma unroll
    for (int o=16;o;o>>=1) m = fmaxf(m, __shfl_xor_sync(0xffffffffu,m,o));
    float sum = 0.f;
    #pragma unroll
    for (int w=0; w<4; w++){
        v[w].x = __expf(v[w].x - m);
        v[w].y = __expf(v[w].y - m);
        v[w].z = __expf(v[w].z - m);
        v[w].w = __expf(v[w].w - m);
        sum += v[w].x+v[w].y+v[w].z+v[w].w;
    }
    #pragma unroll
    for (int o=16;o;o>>=1) sum += __shfl_xor_sync(0xffffffffu,sum,o);
    float inv = __frcp_rn(sum);
    #pragma unroll
    for (int w=0; w<4; w++){
        v[w].x*=inv; v[w].y*=inv; v[w].z*=inv; v[w].w*=inv;
        row[w*32 + lane] = v[w];
    }
}

// ---------------- PV (tensor cores, tf32x3): X += P @ V --------------------
// Out tile 128x64 per (q-tile, z). 8 warps (4m x 2n), warp tile 32x32.
// CLIMIT: causal — P[q][k]==0 for k>q, so stop k-loop at bq+128.
template<bool SELF, bool CLIMIT>
__global__ void __launch_bounds__(256)
pv_tc(const float* __restrict__ S, const float* __restrict__ V,
      float* __restrict__ X) {
    extern __shared__ float2 smraw[];
    float2* Ps = smraw;            // [128][34]
    float2* Vs = smraw + 128*34;   // [32][66]
    const int z = blockIdx.y, b = z >> 4, h = z & 15;
    const float* Pb = S + (size_t)z*Tt*Tt;
    const float* Vb; int vstr;
    if (SELF) { Vb = V + (size_t)(b*Tt)*Dd + h*DHh; vstr = Dd; }
    else      { Vb = V + (size_t)z*Tt*DHh;          vstr = DHh; }
    float* Xb = X + (size_t)(b*Tt)*Dd + h*DHh;
    const int bq = blockIdx.x*128;
    const int tid = threadIdx.x, lane = tid&31, warp = tid>>5;
    const int wm = (warp>>1)*32, wn = (warp&1)*32;
    const int gid = lane>>2, tig = lane&3;
    const int ldr = tid>>1, ldc = (tid&1)*16;       // P loads
    const int vr = tid>>3, vc = (tid&7)*8;          // V loads
    const int kend = CLIMIT ? (bq + 128) : Tt;
    float c[2][4][4] = {};
    float4 pv4[4], vv[2];
    #pragma unroll
    for (int i=0;i<4;i++) pv4[i] = *(const float4*)(Pb + (size_t)(bq+ldr)*Tt + ldc + i*4);
    #pragma unroll
    for (int i=0;i<2;i++) vv[i] = *(const float4*)(Vb + (size_t)vr*vstr + vc + i*4);
    for (int k0=0;k0<kend;k0+=32){
        __syncthreads();
        #pragma unroll
        for (int i=0;i<4;i++){
            const float* p4=(const float*)&pv4[i];
            #pragma unroll
            for (int j=0;j<4;j++) Ps[ldr*34 + ldc + i*4 + j] = f_hilo(p4[j]);
        }
        #pragma unroll
        for (int i=0;i<2;i++){
            const float* v4=(const float*)&vv[i];
            #pragma unroll
            for (int j=0;j<4;j++) Vs[vr*66 + vc + i*4 + j] = f_hilo(v4[j]);
        }
        __syncthreads();
        if (k0+32 < kend){
            #pragma unroll
            for (int i=0;i<4;i++)
                pv4[i] = *(const float4*)(Pb + (size_t)(bq+ldr)*Tt + k0+32 + ldc + i*4);
            #pragma unroll
            for (int i=0;i<2;i++)
                vv[i] = *(const float4*)(Vb + (size_t)(k0+32+vr)*vstr + vc + i*4);
        }
        #pragma unroll
        for (int k8=0;k8<4;k8++){
            const int kb = k8*8;
            uint32_t ahi[2][4], alo[2][4], bhi[4][2], blo[4][2];
            #pragma unroll
            for (int mt=0;mt<2;mt++){
                int mb = wm + mt*16 + gid;
                float2 f0 = Ps[mb*34 + kb+tig];
                float2 f1 = Ps[(mb+8)*34 + kb+tig];
                float2 f2 = Ps[mb*34 + kb+tig+4];
                float2 f3 = Ps[(mb+8)*34 + kb+tig+4];
                ahi[mt][0]=__float_as_uint(f0.x); alo[mt][0]=__float_as_uint(f0.y);
                ahi[mt][1]=__float_as_uint(f1.x); alo[mt][1]=__float_as_uint(f1.y);
                ahi[mt][2]=__float_as_uint(f2.x); alo[mt][2]=__float_as_uint(f2.y);
                ahi[mt][3]=__float_as_uint(f3.x); alo[mt][3]=__float_as_uint(f3.y);
            }
            #pragma unroll
            for (int nt=0;nt<4;nt++){
                int nb = wn + nt*8 + gid;
                float2 g0 = Vs[(kb+tig)*66 + nb];
                float2 g1 = Vs[(kb+tig+4)*66 + nb];
                bhi[nt][0]=__float_as_uint(g0.x); blo[nt][0]=__float_as_uint(g0.y);
                bhi[nt][1]=__float_as_uint(g1.x); blo[nt][1]=__float_as_uint(g1.y);
            }
            #pragma unroll
            for (int mt=0;mt<2;mt++)
                #pragma unroll
                for (int nt=0;nt<4;nt++){
                    mma8(c[mt][nt], ahi[mt], bhi[nt]);
                    mma8(c[mt][nt], alo[mt], bhi[nt]);
                    mma8(c[mt][nt], ahi[mt], blo[nt]);
                }
        }
    }
    #pragma unroll
    for (int mt=0;mt<2;mt++){
        #pragma unroll
        for (int nt=0;nt<4;nt++){
            int col = wn + nt*8 + tig*2;
            #pragma unroll
            for (int half=0; half<2; half++){
                int row = bq + wm + mt*16 + gid + half*8;
                float2* xp = (float2*)(Xb + (size_t)row*Dd + col);
                float2 o = *xp;
                o.x += c[mt][nt][half*2];
                o.y += c[mt][nt][half*2+1];
                *xp = o;
            }
        }
    }
}

// ---------------- ordinal sigmoid head ------------------------------------
__global__ void head_kernel(const float* __restrict__ X,
                            const float* __restrict__ cutoff,
                            float* __restrict__ out) {
    __shared__ float E[9];
    if (threadIdx.x < 9) {
        float bj = cutoff[0];
        for (int j=1;j<=threadIdx.x;j++){ float c = cutoff[j]; bj += c*c; }
        E[threadIdx.x] = __expf(-bj);
    }
    __syncthreads();
    const int n = Mrows*Dd;
    for (int idx = blockIdx.x*blockDim.x + threadIdx.x; idx < n;
         idx += gridDim.x*blockDim.x) {
        float xv = X[idx];
        float ex = __expf(xv);
        float s[9];
        #pragma unroll
        for (int j=0;j<9;j++) s[j] = __fdividef(1.0f, 1.0f + ex*E[j]);
        float2* o2 = (float2*)(out + (size_t)idx*10);
        o2[0] = make_float2(s[0],        s[1]-s[0]);
        o2[1] = make_float2(s[2]-s[1],   s[3]-s[2]);
        o2[2] = make_float2(s[4]-s[3],   s[5]-s[4]);
        o2[3] = make_float2(s[6]-s[5],   s[7]-s[6]);
        o2[4] = make_float2(s[8]-s[7],   1.0f - s[8]);
    }
}

// ---------------- launcher --------------------------------------------------
#define SM_GEMM   (2*128*34*(int)sizeof(float2))              // 69632
#define SM_SCORES (2*128*66*(int)sizeof(float2))              // 135168
#define SM_PV     ((128*34 + 32*66)*(int)sizeof(float2))      // 51712

extern "C" void kernel_launch(void* const* d_in, const int* in_sizes, int n_in,
                              void* d_out, int out_size) {
    (void)in_sizes; (void)n_in; (void)out_size;
    const float* x    = (const float*)d_in[0];
    const float* k    = (const float*)d_in[1];
    const float* v    = (const float*)d_in[2];
    const float* pos  = (const float*)d_in[3];
    const float* Wq1  = (const float*)d_in[4];
    const float* Wk1  = (const float*)d_in[5];
    const float* Wv1  = (const float*)d_in[6];
    const float* Wq2  = (const float*)d_in[7];
    const float* Wfc  = (const float*)d_in[8];
    const float* bfc  = (const float*)d_in[9];
    const float* g1   = (const float*)d_in[10];
    const float* b1   = (const float*)d_in[11];
    const float* g2   = (const float*)d_in[12];
    const float* b2   = (const float*)d_in[13];
    const float* g3   = (const float*)d_in[14];
    const float* b3   = (const float*)d_in[15];
    const float* cut  = (const float*)d_in[16];
    float* out = (float*)d_out;

    float *xa, *xb, *q, *kk, *vv, *S;
    cudaGetSymbolAddress((void**)&xa, g_xa);
    cudaGetSymbolAddress((void**)&xb, g_xb);
    cudaGetSymbolAddress((void**)&q,  g_q);
    cudaGetSymbolAddress((void**)&kk, g_k);
    cudaGetSymbolAddress((void**)&vv, g_v);
    cudaGetSymbolAddress((void**)&S,  g_s);

    // opt-in dynamic smem (idempotent; host-side, capture-safe)
    cudaFuncSetAttribute(gemm_tc<false>, cudaFuncAttributeMaxDynamicSharedMemorySize, SM_GEMM);
    cudaFuncSetAttribute(gemm_tc<true>,  cudaFuncAttributeMaxDynamicSharedMemorySize, SM_GEMM);
    cudaFuncSetAttribute(scores_tc<true,false>,  cudaFuncAttributeMaxDynamicSharedMemorySize, SM_SCORES);
    cudaFuncSetAttribute(scores_tc<false,true>,  cudaFuncAttributeMaxDynamicSharedMemorySize, SM_SCORES);
    cudaFuncSetAttribute(pv_tc<true,false>, cudaFuncAttributeMaxDynamicSharedMemorySize, SM_PV);
    cudaFuncSetAttribute(pv_tc<false,true>, cudaFuncAttributeMaxDynamicSharedMemorySize, SM_PV);

    add_pos_kernel<<<Mrows*Dd/4/256, 256>>>(x, pos, xa);

    float* cur = xa; float* oth = xb;
    const dim3 gGemm(8, 32);
    const dim3 gScores(4, 4, BH);
    const dim3 gPV(4, BH);
    const int gSoft = BH*Tt/8;

    for (int i = 0; i < Ll; i++) {
        if (i) ln_kernel<<<Mrows,256>>>(cur, g1 + (size_t)(i-1)*Dd, b1 + (size_t)(i-1)*Dd);
        // self-attention
        gemm_tc<false><<<gGemm,256,SM_GEMM>>>(cur, Wq1 + (size_t)i*Dd*Dd, nullptr, q);
        gemm_tc<false><<<gGemm,256,SM_GEMM>>>(cur, Wk1 + (size_t)i*Dd*Dd, nullptr, kk);
        gemm_tc<false><<<gGemm,256,SM_GEMM>>>(cur, Wv1 + (size_t)i*Dd*Dd, nullptr, vv);
        scores_tc<true,false><<<gScores,256,SM_SCORES>>>(q, kk, S);
        softmax_kernel<false><<<gSoft,256>>>(S);
        pv_tc<true,false><<<gPV,256,SM_PV>>>(S, vv, cur);
        ln_kernel<<<Mrows,256>>>(cur, g2 + (size_t)i*Dd, b2 + (size_t)i*Dd);
        // cross-attention (causal)
        gemm_tc<false><<<gGemm,256,SM_GEMM>>>(cur, Wq2 + (size_t)i*Dd*Dd, nullptr, q);
        scores_tc<false,true><<<gScores,256,SM_SCORES>>>(q, k, S);
        softmax_kernel<true><<<gSoft,256>>>(S);
        pv_tc<false,true><<<gPV,256,SM_PV>>>(S, v, cur);
        ln_kernel<<<Mrows,256>>>(cur, g3 + (size_t)i*Dd, b3 + (size_t)i*Dd);
        // FC + relu + residual (ping-pong to avoid read/write race)
        gemm_tc<true><<<gGemm,256,SM_GEMM>>>(cur, Wfc + (size_t)i*Dd*Dd, bfc + (size_t)i*Dd, oth);
        float* t = cur; cur = oth; oth = t;
    }

    head_kernel<<<4096,256>>>(cur, cut, out);
}